// round 3
// baseline (speedup 1.0000x reference)
#include <cuda_runtime.h>

// Resampling: 3D affine grid-sample, trilinear, fp32.
// Shapes: fmap (B=16, P=8, H=32, W=32, D=32, C=8), theta (B, 12*P).
//
// Lane-cooperative mapping: 8 lanes per voxel (4 voxels per warp).
//   lane sub-id s = gid & 7 :  zsel = s>>2 (which z corner), c2 = s&3 (float2 channel pair)
// For each of the 4 (y,x) corners, the 8 lanes of one voxel load 64 contiguous
// bytes (both z corners x 8 channels) -> lanes merge into the same 128B line,
// fixing the one-sector-per-lane L1 wavefront waste of the 1-thread-per-voxel
// version. z-blend via shfl_xor(4); zsel==0 lanes store coalesced float2.

#define RS_B 16
#define RS_P 8
#define RS_H 32
#define RS_W 32
#define RS_D 32
#define RS_C 8
#define RS_VOX (RS_H * RS_W * RS_D)   // 32768 voxels per (b,p) slice

__global__ __launch_bounds__(256) void resample_kernel(
    const float* __restrict__ fmap,
    const float* __restrict__ theta,
    float* __restrict__ out)
{
    __shared__ float t[12];

    const int gid   = blockIdx.x * 256 + threadIdx.x;
    const int voxel = gid >> 3;                 // global voxel id
    const int s     = gid & 7;                  // sub-lane within voxel
    const int zsel  = s >> 2;                   // 0 -> z0 corner, 1 -> z1 corner
    const int c2    = s & 3;                    // float2 channel pair index

    const int slice = voxel >> 15;              // b*P + p
    const int n     = voxel & (RS_VOX - 1);

    // theta row: b*96 + p*12 floats — block covers 32 voxels, all in one slice
    if (threadIdx.x < 12) {
        const int bslice = (blockIdx.x * 32) >> 15;
        t[threadIdx.x] = theta[(bslice >> 3) * (12 * RS_P)
                               + (bslice & (RS_P - 1)) * 12 + threadIdx.x];
    }
    __syncthreads();

    // n = (h*W + w)*D + d ; grid point is (xs[w], ys[h], zs[d])
    const int h = n >> 10;
    const int w = (n >> 5) & 31;
    const int d = n & 31;

    const float step = 2.0f / 31.0f;
    const float gx = fmaf((float)w, step, -1.0f);
    const float gy = fmaf((float)h, step, -1.0f);
    const float gz = fmaf((float)d, step, -1.0f);

    const float xp = t[0] * gx + t[1] * gy + t[2]  * gz + t[3];
    const float yp = t[4] * gx + t[5] * gy + t[6]  * gz + t[7];
    const float zp = t[8] * gx + t[9] * gy + t[10] * gz + t[11];

    const float x = 0.5f * (xp + 1.0f) * (float)(RS_W - 2);
    const float y = 0.5f * (yp + 1.0f) * (float)(RS_H - 2);
    const float z = 0.5f * (zp + 1.0f) * (float)(RS_D - 2);

    int x0 = (int)floorf(x); int x1 = x0 + 1;
    int y0 = (int)floorf(y); int y1 = y0 + 1;
    int z0 = (int)floorf(z); int z1 = z0 + 1;
    x0 = min(max(x0, 0), RS_W - 1); x1 = min(max(x1, 0), RS_W - 1);
    y0 = min(max(y0, 0), RS_H - 1); y1 = min(max(y1, 0), RS_H - 1);
    z0 = min(max(z0, 0), RS_D - 1); z1 = min(max(z1, 0), RS_D - 1);

    // weights from CLAMPED corners (reference semantics)
    const float xd = x - (float)x0;        // weight x1; (1-xd) x0
    const float yd = (float)y1 - y;        // weight y0; (1-yd) y1
    const float zd = z - (float)z0;        // weight z1; (1-zd) z0

    const float wx0 = 1.0f - xd, wx1 = xd;
    const float wy0 = yd,        wy1 = 1.0f - yd;
    const float wz0 = 1.0f - zd, wz1 = zd;

    const int zi = zsel ? z1 : z0;         // this lane's z corner

    const float* base = fmap + (size_t)slice * (RS_VOX * RS_C);

    // partial over the 4 (y,x) corners for this lane's z corner & channel pair
    float px = 0.0f, py = 0.0f;

    {
        // (y0,x0)
        const float2 v = __ldg((const float2*)(base + (size_t)((y0 * RS_W + x0) * RS_D + zi) * RS_C) + c2);
        const float wgt = wy0 * wx0;
        px = fmaf(wgt, v.x, px); py = fmaf(wgt, v.y, py);
    }
    {
        // (y0,x1)
        const float2 v = __ldg((const float2*)(base + (size_t)((y0 * RS_W + x1) * RS_D + zi) * RS_C) + c2);
        const float wgt = wy0 * wx1;
        px = fmaf(wgt, v.x, px); py = fmaf(wgt, v.y, py);
    }
    {
        // (y1,x0)
        const float2 v = __ldg((const float2*)(base + (size_t)((y1 * RS_W + x0) * RS_D + zi) * RS_C) + c2);
        const float wgt = wy1 * wx0;
        px = fmaf(wgt, v.x, px); py = fmaf(wgt, v.y, py);
    }
    {
        // (y1,x1)
        const float2 v = __ldg((const float2*)(base + (size_t)((y1 * RS_W + x1) * RS_D + zi) * RS_C) + c2);
        const float wgt = wy1 * wx1;
        px = fmaf(wgt, v.x, px); py = fmaf(wgt, v.y, py);
    }

    // z-blend: exchange partials between zsel=0 and zsel=1 lanes (xor 4)
    const float ox = __shfl_xor_sync(0xffffffffu, px, 4);
    const float oy = __shfl_xor_sync(0xffffffffu, py, 4);

    if (zsel == 0) {
        float2 r;
        r.x = wz0 * px + wz1 * ox;
        r.y = wz0 * py + wz1 * oy;
        ((float2*)(out + (size_t)voxel * RS_C))[c2] = r;
    }
}

extern "C" void kernel_launch(void* const* d_in, const int* in_sizes, int n_in,
                              void* d_out, int out_size)
{
    const float* fmap  = (const float*)d_in[0];
    const float* theta = (const float*)d_in[1];
    float* out = (float*)d_out;

    const int total = RS_B * RS_P * RS_VOX * 8;   // 33,554,432 threads
    resample_kernel<<<total / 256, 256>>>(fmap, theta, out);
}

// round 5
// speedup vs baseline: 1.5000x; 1.5000x over previous
#include <cuda_runtime.h>

// Resampling: 3D affine grid-sample, trilinear, fp32.
// fmap (B=16,P=8,H=32,W=32,D=32,C=8), theta (B,12*P).
//
// 2 lanes per voxel: lane zsel=0 handles corner z0, zsel=1 handles z1.
// Each lane accumulates the 4 (y,x) corners for its z-corner over all 8
// channels (2x LDG.128 per corner, front-batched for MLP). z0/z1 lanes'
// addresses are 32B apart -> same 128B line most of the time; 16
// consecutive-d voxels per warp give dense z spans -> good lane merging
// with only 2x math replication. Final z-blend: one shfl_xor(1) exchange
// of the half the partner finalizes, then a fully-coalesced full-warp
// float4 store (out float4 idx == gid).

#define RS_B 16
#define RS_P 8
#define RS_H 32
#define RS_W 32
#define RS_D 32
#define RS_C 8
#define RS_VOX (RS_H * RS_W * RS_D)   // 32768 voxels per (b,p) slice

__global__ __launch_bounds__(256) void resample_kernel(
    const float* __restrict__ fmap,
    const float* __restrict__ theta,
    float* __restrict__ out)
{
    __shared__ float t[12];

    const int gid   = blockIdx.x * 256 + threadIdx.x;
    const int voxel = gid >> 1;                 // global voxel id
    const int zsel  = gid & 1;                  // which z corner this lane owns

    const int slice = voxel >> 15;              // b*P + p
    const int n     = voxel & (RS_VOX - 1);

    // theta row: b*96 + p*12 floats — block covers 128 voxels, one slice
    if (threadIdx.x < 12) {
        const int bslice = (blockIdx.x * 128) >> 15;
        t[threadIdx.x] = theta[(bslice >> 3) * (12 * RS_P)
                               + (bslice & (RS_P - 1)) * 12 + threadIdx.x];
    }
    __syncthreads();

    // n = (h*W + w)*D + d ; grid point is (xs[w], ys[h], zs[d])
    const int h = n >> 10;
    const int w = (n >> 5) & 31;
    const int d = n & 31;

    const float step = 2.0f / 31.0f;
    const float gx = fmaf((float)w, step, -1.0f);
    const float gy = fmaf((float)h, step, -1.0f);
    const float gz = fmaf((float)d, step, -1.0f);

    const float xp = t[0] * gx + t[1] * gy + t[2]  * gz + t[3];
    const float yp = t[4] * gx + t[5] * gy + t[6]  * gz + t[7];
    const float zp = t[8] * gx + t[9] * gy + t[10] * gz + t[11];

    const float x = 0.5f * (xp + 1.0f) * (float)(RS_W - 2);
    const float y = 0.5f * (yp + 1.0f) * (float)(RS_H - 2);
    const float z = 0.5f * (zp + 1.0f) * (float)(RS_D - 2);

    int x0 = (int)floorf(x); int x1 = x0 + 1;
    int y0 = (int)floorf(y); int y1 = y0 + 1;
    int z0 = (int)floorf(z); int z1 = z0 + 1;
    x0 = min(max(x0, 0), RS_W - 1); x1 = min(max(x1, 0), RS_W - 1);
    y0 = min(max(y0, 0), RS_H - 1); y1 = min(max(y1, 0), RS_H - 1);
    z0 = min(max(z0, 0), RS_D - 1); z1 = min(max(z1, 0), RS_D - 1);

    // weights from CLAMPED corners (reference semantics)
    const float xd = x - (float)x0;        // weight x1; (1-xd) x0
    const float yd = (float)y1 - y;        // weight y0; (1-yd) y1
    const float zd = z - (float)z0;        // weight z1; (1-zd) z0

    const float wx0 = 1.0f - xd, wx1 = xd;
    const float wy0 = yd,        wy1 = 1.0f - yd;
    const float wz0 = 1.0f - zd, wz1 = zd;

    const int zi = zsel ? z1 : z0;         // this lane's z corner

    const float* base = fmap + (size_t)slice * (RS_VOX * RS_C)
                             + (size_t)zi * RS_C;

    const float w00 = wy0 * wx0;
    const float w01 = wy0 * wx1;
    const float w10 = wy1 * wx0;
    const float w11 = wy1 * wx1;

    const float4* p00 = (const float4*)(base + (y0 * RS_W + x0) * (RS_D * RS_C));
    const float4* p01 = (const float4*)(base + (y0 * RS_W + x1) * (RS_D * RS_C));
    const float4* p10 = (const float4*)(base + (y1 * RS_W + x0) * (RS_D * RS_C));
    const float4* p11 = (const float4*)(base + (y1 * RS_W + x1) * (RS_D * RS_C));

    // front-batched loads (max MLP)
    const float4 lo00 = __ldg(p00), hi00 = __ldg(p00 + 1);
    const float4 lo01 = __ldg(p01), hi01 = __ldg(p01 + 1);
    const float4 lo10 = __ldg(p10), hi10 = __ldg(p10 + 1);
    const float4 lo11 = __ldg(p11), hi11 = __ldg(p11 + 1);

    float4 alo, ahi;
    alo.x = w00 * lo00.x; alo.y = w00 * lo00.y; alo.z = w00 * lo00.z; alo.w = w00 * lo00.w;
    ahi.x = w00 * hi00.x; ahi.y = w00 * hi00.y; ahi.z = w00 * hi00.z; ahi.w = w00 * hi00.w;

    alo.x = fmaf(w01, lo01.x, alo.x); alo.y = fmaf(w01, lo01.y, alo.y);
    alo.z = fmaf(w01, lo01.z, alo.z); alo.w = fmaf(w01, lo01.w, alo.w);
    ahi.x = fmaf(w01, hi01.x, ahi.x); ahi.y = fmaf(w01, hi01.y, ahi.y);
    ahi.z = fmaf(w01, hi01.z, ahi.z); ahi.w = fmaf(w01, hi01.w, ahi.w);

    alo.x = fmaf(w10, lo10.x, alo.x); alo.y = fmaf(w10, lo10.y, alo.y);
    alo.z = fmaf(w10, lo10.z, alo.z); alo.w = fmaf(w10, lo10.w, alo.w);
    ahi.x = fmaf(w10, hi10.x, ahi.x); ahi.y = fmaf(w10, hi10.y, ahi.y);
    ahi.z = fmaf(w10, hi10.z, ahi.z); ahi.w = fmaf(w10, hi10.w, ahi.w);

    alo.x = fmaf(w11, lo11.x, alo.x); alo.y = fmaf(w11, lo11.y, alo.y);
    alo.z = fmaf(w11, lo11.z, alo.z); alo.w = fmaf(w11, lo11.w, alo.w);
    ahi.x = fmaf(w11, hi11.x, ahi.x); ahi.y = fmaf(w11, hi11.y, ahi.y);
    ahi.z = fmaf(w11, hi11.z, ahi.z); ahi.w = fmaf(w11, hi11.w, ahi.w);

    // Exchange with partner lane (voxel's other z corner):
    //   zsel=0 lane finalizes channels 0-3 (needs partner's alo)
    //   zsel=1 lane finalizes channels 4-7 (needs partner's ahi)
    // Each lane SENDS the half its partner finalizes.
    float4 sendv = zsel ? alo : ahi;
    float4 recv;
    recv.x = __shfl_xor_sync(0xffffffffu, sendv.x, 1);
    recv.y = __shfl_xor_sync(0xffffffffu, sendv.y, 1);
    recv.z = __shfl_xor_sync(0xffffffffu, sendv.z, 1);
    recv.w = __shfl_xor_sync(0xffffffffu, sendv.w, 1);

    const float4 mine = zsel ? ahi : alo;        // the half I finalize
    const float wmine  = zsel ? wz1 : wz0;       // weight of my z corner
    const float wother = zsel ? wz0 : wz1;       // weight of partner's corner

    float4 r;
    r.x = wmine * mine.x + wother * recv.x;
    r.y = wmine * mine.y + wother * recv.y;
    r.z = wmine * mine.z + wother * recv.z;
    r.w = wmine * mine.w + wother * recv.w;

    // out float4 index == gid : voxel*2 + zsel -> fully coalesced STG.128
    ((float4*)out)[gid] = r;
}

extern "C" void kernel_launch(void* const* d_in, const int* in_sizes, int n_in,
                              void* d_out, int out_size)
{
    const float* fmap  = (const float*)d_in[0];
    const float* theta = (const float*)d_in[1];
    float* out = (float*)d_out;

    const int total = RS_B * RS_P * RS_VOX * 2;   // 8,388,608 threads
    resample_kernel<<<total / 256, 256>>>(fmap, theta, out);
}

// round 8
// speedup vs baseline: 1.6525x; 1.1017x over previous
#include <cuda_runtime.h>

// Resampling: 3D affine grid-sample, trilinear, fp32.
// fmap (B=16,P=8,H=32,W=32,D=32,C=8), theta (B,12*P).
//
// 4 lanes per voxel: s = (zsel = s>>1, chalf = s&1). For each of the 4 (y,x)
// corners, ONE LDG.128 instruction fetches the voxel's full 64B z-span
// (z0*32 .. z1*32+31, contiguous since z1=z0+1) -> no duplicate-line hi
// loads (R5 paid 2 wavefront touches per corner for data in one line).
// 8 voxels per warp keeps math replication cheap enough (issue ~55-60%).
// z-blend via shfl_xor(2); zsel==0 lanes store float4 (contiguous 256B/warp).

#define RS_B 16
#define RS_P 8
#define RS_H 32
#define RS_W 32
#define RS_D 32
#define RS_C 8
#define RS_VOX (RS_H * RS_W * RS_D)   // 32768 voxels per (b,p) slice

__global__ __launch_bounds__(256) void resample_kernel(
    const float* __restrict__ fmap,
    const float* __restrict__ theta,
    float* __restrict__ out)
{
    __shared__ float t[12];

    const int gid   = blockIdx.x * 256 + threadIdx.x;
    const int voxel = gid >> 2;                 // global voxel id
    const int s     = gid & 3;
    const int zsel  = s >> 1;                   // which z corner this lane owns
    const int chalf = s & 1;                    // which float4 channel half

    const int slice = voxel >> 15;              // b*P + p
    const int n     = voxel & (RS_VOX - 1);

    // theta row: b*96 + p*12 floats — block covers 64 voxels, one slice
    if (threadIdx.x < 12) {
        const int bslice = (blockIdx.x * 64) >> 15;
        t[threadIdx.x] = theta[(bslice >> 3) * (12 * RS_P)
                               + (bslice & (RS_P - 1)) * 12 + threadIdx.x];
    }
    __syncthreads();

    // n = (h*W + w)*D + d ; grid point is (xs[w], ys[h], zs[d])
    const int h = n >> 10;
    const int w = (n >> 5) & 31;
    const int d = n & 31;

    const float step = 2.0f / 31.0f;
    const float gx = fmaf((float)w, step, -1.0f);
    const float gy = fmaf((float)h, step, -1.0f);
    const float gz = fmaf((float)d, step, -1.0f);

    const float xp = t[0] * gx + t[1] * gy + t[2]  * gz + t[3];
    const float yp = t[4] * gx + t[5] * gy + t[6]  * gz + t[7];
    const float zp = t[8] * gx + t[9] * gy + t[10] * gz + t[11];

    const float x = 0.5f * (xp + 1.0f) * (float)(RS_W - 2);
    const float y = 0.5f * (yp + 1.0f) * (float)(RS_H - 2);
    const float z = 0.5f * (zp + 1.0f) * (float)(RS_D - 2);

    int x0 = (int)floorf(x); int x1 = x0 + 1;
    int y0 = (int)floorf(y); int y1 = y0 + 1;
    int z0 = (int)floorf(z); int z1 = z0 + 1;
    x0 = min(max(x0, 0), RS_W - 1); x1 = min(max(x1, 0), RS_W - 1);
    y0 = min(max(y0, 0), RS_H - 1); y1 = min(max(y1, 0), RS_H - 1);
    z0 = min(max(z0, 0), RS_D - 1); z1 = min(max(z1, 0), RS_D - 1);

    // weights from CLAMPED corners (reference semantics)
    const float xd = x - (float)x0;        // weight x1; (1-xd) x0
    const float yd = (float)y1 - y;        // weight y0; (1-yd) y1
    const float zd = z - (float)z0;        // weight z1; (1-zd) z0

    const float wx0 = 1.0f - xd, wx1 = xd;
    const float wy0 = yd,        wy1 = 1.0f - yd;
    const float wz0 = 1.0f - zd, wz1 = zd;

    const int zi = zsel ? z1 : z0;         // this lane's z corner

    // this lane's float4 within the corner span: zi*C + chalf*4 floats
    const float* base = fmap + (size_t)slice * (RS_VOX * RS_C)
                             + (size_t)zi * RS_C + (size_t)chalf * 4;

    const float w00 = wy0 * wx0;
    const float w01 = wy0 * wx1;
    const float w10 = wy1 * wx0;
    const float w11 = wy1 * wx1;

    const int r00 = (y0 * RS_W + x0) * (RS_D * RS_C);
    const int r01 = (y0 * RS_W + x1) * (RS_D * RS_C);
    const int r10 = (y1 * RS_W + x0) * (RS_D * RS_C);
    const int r11 = (y1 * RS_W + x1) * (RS_D * RS_C);

    // front-batched loads: one LDG.128 per (y,x) corner per lane
    const float4 v00 = __ldg((const float4*)(base + r00));
    const float4 v01 = __ldg((const float4*)(base + r01));
    const float4 v10 = __ldg((const float4*)(base + r10));
    const float4 v11 = __ldg((const float4*)(base + r11));

    float4 acc;
    acc.x = w00 * v00.x; acc.y = w00 * v00.y; acc.z = w00 * v00.z; acc.w = w00 * v00.w;
    acc.x = fmaf(w01, v01.x, acc.x); acc.y = fmaf(w01, v01.y, acc.y);
    acc.z = fmaf(w01, v01.z, acc.z); acc.w = fmaf(w01, v01.w, acc.w);
    acc.x = fmaf(w10, v10.x, acc.x); acc.y = fmaf(w10, v10.y, acc.y);
    acc.z = fmaf(w10, v10.z, acc.z); acc.w = fmaf(w10, v10.w, acc.w);
    acc.x = fmaf(w11, v11.x, acc.x); acc.y = fmaf(w11, v11.y, acc.y);
    acc.z = fmaf(w11, v11.z, acc.z); acc.w = fmaf(w11, v11.w, acc.w);

    // z-blend: partner lane is same chalf, other zsel (xor 2)
    float4 recv;
    recv.x = __shfl_xor_sync(0xffffffffu, acc.x, 2);
    recv.y = __shfl_xor_sync(0xffffffffu, acc.y, 2);
    recv.z = __shfl_xor_sync(0xffffffffu, acc.z, 2);
    recv.w = __shfl_xor_sync(0xffffffffu, acc.w, 2);

    if (zsel == 0) {
        float4 r;
        r.x = wz0 * acc.x + wz1 * recv.x;
        r.y = wz0 * acc.y + wz1 * recv.y;
        r.z = wz0 * acc.z + wz1 * recv.z;
        r.w = wz0 * acc.w + wz1 * recv.w;
        // out float4 index voxel*2 + chalf -> warp writes 256B contiguous
        ((float4*)out)[voxel * 2 + chalf] = r;
    }
}

extern "C" void kernel_launch(void* const* d_in, const int* in_sizes, int n_in,
                              void* d_out, int out_size)
{
    const float* fmap  = (const float*)d_in[0];
    const float* theta = (const float*)d_in[1];
    float* out = (float*)d_out;

    const int total = RS_B * RS_P * RS_VOX * 4;   // 16,777,216 threads
    resample_kernel<<<total / 256, 256>>>(fmap, theta, out);
}